// round 10
// baseline (speedup 1.0000x reference)
#include <cuda_runtime.h>
#include <cuda_bf16.h>
#include <math_constants.h>
#include <cstdint>

#define SEQ 2048
#define HID 1024
#define NH  16
#define HD  64
#define QKV_N (3 * HID)

// ---------------------------------------------------------------------------
// Scratch (no dynamic allocation allowed)
// ---------------------------------------------------------------------------
__device__ __align__(128) __nv_bfloat16 g_Ah[SEQ * HID];
__device__ __align__(128) __nv_bfloat16 g_Al[SEQ * HID];
__device__ __align__(128) __nv_bfloat16 g_Wah[QKV_N * HID];
__device__ __align__(128) __nv_bfloat16 g_Wal[QKV_N * HID];
__device__ __align__(128) __nv_bfloat16 g_Wph[HID * HID];
__device__ __align__(128) __nv_bfloat16 g_Wpl[HID * HID];
__device__ __align__(128) __nv_bfloat16 g_Ch[SEQ * HID];
__device__ __align__(128) __nv_bfloat16 g_Cl[SEQ * HID];
// per-head QKV, bf16 hi/lo, layout [NH][SEQ][64]
__device__ __align__(128) __nv_bfloat16 g_Qh[NH * SEQ * HD];
__device__ __align__(128) __nv_bfloat16 g_Ql[NH * SEQ * HD];
__device__ __align__(128) __nv_bfloat16 g_Kh[NH * SEQ * HD];
__device__ __align__(128) __nv_bfloat16 g_Kl[NH * SEQ * HD];
__device__ __align__(128) __nv_bfloat16 g_Vh[NH * SEQ * HD];
__device__ __align__(128) __nv_bfloat16 g_Vl[NH * SEQ * HD];

// ---------------------------------------------------------------------------
// Helpers (baseline PTX only)
// ---------------------------------------------------------------------------
__device__ __forceinline__ uint32_t smem_u32(const void* p) {
    uint32_t a;
    asm("{ .reg .u64 t; cvta.to.shared.u64 t, %1; cvt.u32.u64 %0, t; }"
        : "=r"(a) : "l"(p));
    return a;
}
__device__ __forceinline__ void cp_async16(uint32_t dst, const void* src) {
    asm volatile("cp.async.cg.shared.global [%0], [%1], 16;"
                 :: "r"(dst), "l"(src));
}
#define CP_COMMIT() asm volatile("cp.async.commit_group;" ::: "memory")
#define CP_WAIT(n)  asm volatile("cp.async.wait_group %0;" :: "n"(n) : "memory")

__device__ __forceinline__ void ldm_x4(uint32_t* r, uint32_t addr) {
    asm volatile("ldmatrix.sync.aligned.m8n8.x4.shared.b16 {%0,%1,%2,%3}, [%4];"
                 : "=r"(r[0]), "=r"(r[1]), "=r"(r[2]), "=r"(r[3]) : "r"(addr));
}
__device__ __forceinline__ void ldm_x4_t(uint32_t* r, uint32_t addr) {
    asm volatile("ldmatrix.sync.aligned.m8n8.x4.trans.shared.b16 {%0,%1,%2,%3}, [%4];"
                 : "=r"(r[0]), "=r"(r[1]), "=r"(r[2]), "=r"(r[3]) : "r"(addr));
}
__device__ __forceinline__ void mma_bf16(float* d, const uint32_t* a,
                                         uint32_t b0, uint32_t b1) {
    asm volatile(
        "mma.sync.aligned.m16n8k16.row.col.f32.bf16.bf16.f32 "
        "{%0,%1,%2,%3}, {%4,%5,%6,%7}, {%8,%9}, {%0,%1,%2,%3};"
        : "+f"(d[0]), "+f"(d[1]), "+f"(d[2]), "+f"(d[3])
        : "r"(a[0]), "r"(a[1]), "r"(a[2]), "r"(a[3]), "r"(b0), "r"(b1));
}
__device__ __forceinline__ uint32_t pack_bf16(float a, float b) {
    __nv_bfloat162 t;
    t.x = __float2bfloat16(a);
    t.y = __float2bfloat16(b);
    return *reinterpret_cast<uint32_t*>(&t);
}

// ---------------------------------------------------------------------------
// Conversion kernels
// ---------------------------------------------------------------------------
__global__ void cvt_hilo(const float* __restrict__ x,
                         __nv_bfloat16* __restrict__ hi,
                         __nv_bfloat16* __restrict__ lo, int n4) {
    int i = blockIdx.x * blockDim.x + threadIdx.x;
    if (i >= n4) return;
    float4 v = reinterpret_cast<const float4*>(x)[i];
    __nv_bfloat16 h0 = __float2bfloat16(v.x), h1 = __float2bfloat16(v.y);
    __nv_bfloat16 h2 = __float2bfloat16(v.z), h3 = __float2bfloat16(v.w);
    uint2 hw, lw;
    hw.x = pack_bf16(v.x, v.y);
    hw.y = pack_bf16(v.z, v.w);
    lw.x = pack_bf16(v.x - __bfloat162float(h0), v.y - __bfloat162float(h1));
    lw.y = pack_bf16(v.z - __bfloat162float(h2), v.w - __bfloat162float(h3));
    reinterpret_cast<uint2*>(hi)[i] = hw;
    reinterpret_cast<uint2*>(lo)[i] = lw;
}

__global__ void cvt_transpose(const float* __restrict__ w,
                              __nv_bfloat16* __restrict__ th,
                              __nv_bfloat16* __restrict__ tl,
                              int K, int N) {
    __shared__ float tile[32][33];
    int n0 = blockIdx.x * 32, k0 = blockIdx.y * 32;
    int tx = threadIdx.x, ty = threadIdx.y;
#pragma unroll
    for (int j = 0; j < 4; j++)
        tile[ty + 8 * j][tx] = w[(size_t)(k0 + ty + 8 * j) * N + n0 + tx];
    __syncthreads();
#pragma unroll
    for (int j = 0; j < 4; j++) {
        float v = tile[tx][ty + 8 * j];
        __nv_bfloat16 h = __float2bfloat16(v);
        __nv_bfloat16 l = __float2bfloat16(v - __bfloat162float(h));
        size_t o = (size_t)(n0 + ty + 8 * j) * K + k0 + tx;
        th[o] = h;
        tl[o] = l;
    }
}

// ---------------------------------------------------------------------------
// bf16x3 GEMM, 4-stage cp.async pipeline, TERM-MAJOR MMA ordering
// (consecutive MMAs hit distinct accumulators -> no RAW chain).
// mode 0: fp32 C + bias. mode 1: QKV split hi/lo per head.
// ---------------------------------------------------------------------------
#define PITCH 80
#define MAT_BYTES (128 * PITCH)
#define STAGE_BYTES (4 * MAT_BYTES)   // 40960
#define NST 4

__global__ __launch_bounds__(256, 1) void gemm_mma_bf16x3(
    int M, int N, int K, int mode,
    const __nv_bfloat16* __restrict__ Ah, const __nv_bfloat16* __restrict__ Al,
    const __nv_bfloat16* __restrict__ Bh, const __nv_bfloat16* __restrict__ Bl,
    const float* __restrict__ bias, float* __restrict__ C,
    __nv_bfloat16* __restrict__ qh, __nv_bfloat16* __restrict__ ql,
    __nv_bfloat16* __restrict__ kh, __nv_bfloat16* __restrict__ kl,
    __nv_bfloat16* __restrict__ vh, __nv_bfloat16* __restrict__ vl)
{
    extern __shared__ char sm[];
    const uint32_t sbase = smem_u32(sm);
    const int tid = threadIdx.x;
    const int lane = tid & 31;
    const int warp = tid >> 5;
    const int wm = warp & 3;
    const int wn = warp >> 2;
    const int m0 = blockIdx.y * 128;
    const int n0 = blockIdx.x * 128;

    const __nv_bfloat16* srcs[4] = {
        Ah + (size_t)m0 * K, Al + (size_t)m0 * K,
        Bh + (size_t)n0 * K, Bl + (size_t)n0 * K };

    float acc[2][8][4];
#pragma unroll
    for (int i = 0; i < 2; i++)
#pragma unroll
        for (int j = 0; j < 8; j++)
#pragma unroll
            for (int q = 0; q < 4; q++) acc[i][j][q] = 0.0f;

    auto load_stage = [&](int s, int kc) {
#pragma unroll
        for (int i = 0; i < 8; i++) {
            int t = tid + i * 256;
            int mat = t >> 9;
            int r = (t >> 2) & 127;
            int ch = t & 3;
            cp_async16(sbase + s * STAGE_BYTES + mat * MAT_BYTES + r * PITCH + ch * 16,
                       srcs[mat] + (size_t)r * K + kc * 32 + ch * 8);
        }
    };

    const int NC = K / 32;
#pragma unroll
    for (int s = 0; s < NST - 1; s++) {
        load_stage(s, s);
        CP_COMMIT();
    }

    const int g = lane >> 3;
    const int rl = lane & 7;

    for (int c = 0; c < NC; c++) {
        CP_WAIT(NST - 2);
        __syncthreads();

        const uint32_t st = sbase + (c % NST) * STAGE_BYTES;

#pragma unroll
        for (int k16 = 0; k16 < 2; k16++) {
            const int ch = k16 * 2 + (g >> 1);
            const int roff = rl + ((g & 1) << 3);

            uint32_t ah[2][4], al_[2][4];
#pragma unroll
            for (int mf = 0; mf < 2; mf++) {
                int row = wm * 32 + mf * 16 + roff;
                ldm_x4(ah[mf],  st + 0 * MAT_BYTES + row * PITCH + ch * 16);
                ldm_x4(al_[mf], st + 1 * MAT_BYTES + row * PITCH + ch * 16);
            }

            uint32_t bh_[8][2], bl_[8][2];
#pragma unroll
            for (int ng = 0; ng < 4; ng++) {
                int row = wn * 64 + ng * 16 + roff;
                uint32_t r4[4], r5[4];
                ldm_x4(r4, st + 2 * MAT_BYTES + row * PITCH + ch * 16);
                ldm_x4(r5, st + 3 * MAT_BYTES + row * PITCH + ch * 16);
                bh_[2 * ng][0] = r4[0];     bh_[2 * ng][1] = r4[2];
                bh_[2 * ng + 1][0] = r4[1]; bh_[2 * ng + 1][1] = r4[3];
                bl_[2 * ng][0] = r5[0];     bl_[2 * ng][1] = r5[2];
                bl_[2 * ng + 1][0] = r5[1]; bl_[2 * ng + 1][1] = r5[3];
            }

            // term-major: 16 independent accumulators per sweep
#pragma unroll
            for (int mf = 0; mf < 2; mf++)
#pragma unroll
                for (int nf = 0; nf < 8; nf++)
                    mma_bf16(acc[mf][nf], ah[mf],  bh_[nf][0], bh_[nf][1]);
#pragma unroll
            for (int mf = 0; mf < 2; mf++)
#pragma unroll
                for (int nf = 0; nf < 8; nf++)
                    mma_bf16(acc[mf][nf], ah[mf],  bl_[nf][0], bl_[nf][1]);
#pragma unroll
            for (int mf = 0; mf < 2; mf++)
#pragma unroll
                for (int nf = 0; nf < 8; nf++)
                    mma_bf16(acc[mf][nf], al_[mf], bh_[nf][0], bh_[nf][1]);
        }

        if (c + NST - 1 < NC)
            load_stage((c + NST - 1) % NST, c + NST - 1);
        CP_COMMIT();
    }

    // Epilogue
#pragma unroll
    for (int mf = 0; mf < 2; mf++) {
        int rbase = m0 + wm * 32 + mf * 16 + (lane >> 2);
#pragma unroll
        for (int nf = 0; nf < 8; nf++) {
            int col = n0 + wn * 64 + nf * 8 + (lane & 3) * 2;
            float2 bv = *reinterpret_cast<const float2*>(&bias[col]);
            float a0 = acc[mf][nf][0] + bv.x, a1 = acc[mf][nf][1] + bv.y;
            float a2 = acc[mf][nf][2] + bv.x, a3 = acc[mf][nf][3] + bv.y;
            if (mode == 0) {
                float2 o0 = {a0, a1}, o1 = {a2, a3};
                *reinterpret_cast<float2*>(&C[(size_t)rbase * N + col]) = o0;
                *reinterpret_cast<float2*>(&C[(size_t)(rbase + 8) * N + col]) = o1;
            } else {
                int sec = col >> 10;
                int head = (col & 1023) >> 6;
                int dim = col & 63;
                __nv_bfloat16* dh = (sec == 0) ? qh : (sec == 1) ? kh : vh;
                __nv_bfloat16* dl = (sec == 0) ? ql : (sec == 1) ? kl : vl;
                size_t o0 = ((size_t)head * SEQ + rbase) * HD + dim;
                size_t o1 = o0 + 8 * HD;
                __nv_bfloat16 h0 = __float2bfloat16(a0), h1 = __float2bfloat16(a1);
                __nv_bfloat16 h2 = __float2bfloat16(a2), h3 = __float2bfloat16(a3);
                *reinterpret_cast<uint32_t*>(&dh[o0]) = pack_bf16(a0, a1);
                *reinterpret_cast<uint32_t*>(&dl[o0]) =
                    pack_bf16(a0 - __bfloat162float(h0), a1 - __bfloat162float(h1));
                *reinterpret_cast<uint32_t*>(&dh[o1]) = pack_bf16(a2, a3);
                *reinterpret_cast<uint32_t*>(&dl[o1]) =
                    pack_bf16(a2 - __bfloat162float(h2), a3 - __bfloat162float(h3));
            }
        }
    }
}

// ---------------------------------------------------------------------------
// Tensorized causal flash attention, 128-query tiles, term-major MMA order.
// Block = (128 queries, 1 head), 256 threads = 8 warps x 16 rows.
// ---------------------------------------------------------------------------
__global__ __launch_bounds__(256, 1) void attn_mma(
    const __nv_bfloat16* __restrict__ Qh_, const __nv_bfloat16* __restrict__ Ql_,
    const __nv_bfloat16* __restrict__ Kh_, const __nv_bfloat16* __restrict__ Kl_,
    const __nv_bfloat16* __restrict__ Vh_, const __nv_bfloat16* __restrict__ Vl_,
    __nv_bfloat16* __restrict__ Ch, __nv_bfloat16* __restrict__ Cl)
{
    extern __shared__ char sm[];
    const uint32_t sb = smem_u32(sm);
    const int h = blockIdx.y;
    const int qb = blockIdx.x;
    const int tid = threadIdx.x;
    const int lane = tid & 31;
    const int warp = tid >> 5;
    const int qbase = qb * 128;
    const size_t hb = (size_t)h * SEQ * HD;
    const float scale = 0.125f;

    const __nv_bfloat16* kv[4] = { Kh_ + hb, Kl_ + hb, Vh_ + hb, Vl_ + hb };

    // ---- Load Q tile (128 rows, hi/lo) to smem, extract A-fragments ----
    for (int i = tid; i < 128 * 8; i += 256) {
        int r = i >> 3, ch = i & 7;
        uint32_t sw = (uint32_t)((ch ^ (r & 7)) * 16);
        const size_t go = hb + (size_t)(qbase + r) * HD + ch * 8;
        cp_async16(sb + r * 128 + sw, Qh_ + go);
        cp_async16(sb + 16384 + r * 128 + sw, Ql_ + go);
    }
    CP_COMMIT(); CP_WAIT(0);
    __syncthreads();

    uint32_t qh[4][4], ql[4][4];
    {
        int row = warp * 16 + (lane & 15);
#pragma unroll
        for (int ks = 0; ks < 4; ks++) {
            int ch = ks * 2 + (lane >> 4);
            uint32_t a = sb + row * 128 + ((ch ^ (row & 7)) * 16);
            ldm_x4(qh[ks], a);
            ldm_x4(ql[ks], a + 16384);
        }
    }
    __syncthreads();

    float o[8][4];
#pragma unroll
    for (int i = 0; i < 8; i++)
#pragma unroll
        for (int j = 0; j < 4; j++) o[i][j] = 0.0f;
    float m0v = -CUDART_INF_F, m1v = -CUDART_INF_F;
    float l0v = 0.0f, l1v = 0.0f;

    auto load_kv = [&](int s, int t) {
#pragma unroll
        for (int i = 0; i < 8; i++) {
            int idx = tid + i * 256;
            int mat = idx >> 9;
            int r = (idx >> 3) & 63;
            int ch = idx & 7;
            cp_async16(sb + s * 32768 + mat * 8192 + r * 128 + ((ch ^ (r & 7)) * 16),
                       kv[mat] + (size_t)(t * 64 + r) * HD + ch * 8);
        }
        CP_COMMIT();
    };

    load_kv(0, 0);

    const int ntiles = 2 * qb + 2;
    for (int t = 0; t < ntiles; t++) {
        if (t + 1 < ntiles) {
            load_kv((t + 1) & 1, t + 1);
            CP_WAIT(1);
        } else {
            CP_WAIT(0);
        }
        __syncthreads();

        const uint32_t st = sb + (t & 1) * 32768;
        const bool active = (t * 64 <= qbase + warp * 16 + 15);

        if (active) {
            // ---- S = Q K^T (hi/lo 3-MMA, kg pairs, term-major) ----
            float s[8][4];
#pragma unroll
            for (int i = 0; i < 8; i++)
#pragma unroll
                for (int j = 0; j < 4; j++) s[i][j] = 0.0f;

#pragma unroll
            for (int ks = 0; ks < 4; ks++) {
#pragma unroll
                for (int kp = 0; kp < 2; kp++) {
                    uint32_t rh[2][4], rl[2][4];
#pragma unroll
                    for (int j = 0; j < 2; j++) {
                        int key = (kp * 2 + j) * 16 + (lane & 15);
                        int ch = ks * 2 + (lane >> 4);
                        uint32_t a = st + key * 128 + ((ch ^ (key & 7)) * 16);
                        ldm_x4(rh[j], a);            // Kh
                        ldm_x4(rl[j], a + 8192);     // Kl
                    }
                    float* s0 = s[4 * kp + 0];
                    float* s1 = s[4 * kp + 1];
                    float* s2 = s[4 * kp + 2];
                    float* s3 = s[4 * kp + 3];
                    // hh
                    mma_bf16(s0, qh[ks], rh[0][0], rh[0][2]);
                    mma_bf16(s1, qh[ks], rh[0][1], rh[0][3]);
                    mma_bf16(s2, qh[ks], rh[1][0], rh[1][2]);
                    mma_bf16(s3, qh[ks], rh[1][1], rh[1][3]);
                    // h(K-lo)
                    mma_bf16(s0, qh[ks], rl[0][0], rl[0][2]);
                    mma_bf16(s1, qh[ks], rl[0][1], rl[0][3]);
                    mma_bf16(s2, qh[ks], rl[1][0], rl[1][2]);
                    mma_bf16(s3, qh[ks], rl[1][1], rl[1][3]);
                    // (Q-lo)h
                    mma_bf16(s0, ql[ks], rh[0][0], rh[0][2]);
                    mma_bf16(s1, ql[ks], rh[0][1], rh[0][3]);
                    mma_bf16(s2, ql[ks], rh[1][0], rh[1][2]);
                    mma_bf16(s3, ql[ks], rh[1][1], rh[1][3]);
                }
            }

            // ---- scale + causal mask + online softmax ----
            const bool masked = (t >= 2 * qb);
            const int gr = lane >> 2;
            const int c2 = (lane & 3) * 2;
            const int gq0 = qbase + warp * 16 + gr;
            float mx0 = -CUDART_INF_F, mx1 = -CUDART_INF_F;
#pragma unroll
            for (int nf = 0; nf < 8; nf++) {
#pragma unroll
                for (int j = 0; j < 2; j++) {
                    s[nf][j]     *= scale;
                    s[nf][2 + j] *= scale;
                    if (masked) {
                        int gk = t * 64 + nf * 8 + c2 + j;
                        if (gk > gq0)     s[nf][j]     = -CUDART_INF_F;
                        if (gk > gq0 + 8) s[nf][2 + j] = -CUDART_INF_F;
                    }
                    mx0 = fmaxf(mx0, s[nf][j]);
                    mx1 = fmaxf(mx1, s[nf][2 + j]);
                }
            }
            mx0 = fmaxf(mx0, __shfl_xor_sync(0xffffffffu, mx0, 1));
            mx0 = fmaxf(mx0, __shfl_xor_sync(0xffffffffu, mx0, 2));
            mx1 = fmaxf(mx1, __shfl_xor_sync(0xffffffffu, mx1, 1));
            mx1 = fmaxf(mx1, __shfl_xor_sync(0xffffffffu, mx1, 2));

            float mn0 = fmaxf(m0v, mx0), mn1 = fmaxf(m1v, mx1);
            float sum0 = 0.0f, sum1 = 0.0f;
#pragma unroll
            for (int nf = 0; nf < 8; nf++) {
#pragma unroll
                for (int j = 0; j < 2; j++) {
                    float p0 = __expf(s[nf][j] - mn0);
                    float p1 = __expf(s[nf][2 + j] - mn1);
                    s[nf][j] = p0;
                    s[nf][2 + j] = p1;
                    sum0 += p0;
                    sum1 += p1;
                }
            }
            sum0 += __shfl_xor_sync(0xffffffffu, sum0, 1);
            sum0 += __shfl_xor_sync(0xffffffffu, sum0, 2);
            sum1 += __shfl_xor_sync(0xffffffffu, sum1, 1);
            sum1 += __shfl_xor_sync(0xffffffffu, sum1, 2);

            float corr0 = __expf(m0v - mn0), corr1 = __expf(m1v - mn1);
            l0v = l0v * corr0 + sum0;
            l1v = l1v * corr1 + sum1;
            m0v = mn0; m1v = mn1;
#pragma unroll
            for (int nf = 0; nf < 8; nf++) {
                o[nf][0] *= corr0; o[nf][1] *= corr0;
                o[nf][2] *= corr1; o[nf][3] *= corr1;
            }

            // ---- O += P V (hi/lo 3-MMA, dg pairs, term-major) ----
#pragma unroll
            for (int ks = 0; ks < 4; ks++) {
                uint32_t pah[4], pal[4];
#pragma unroll
                for (int half = 0; half < 2; half++) {
                    float p0 = s[2 * ks + half][0], p1 = s[2 * ks + half][1];
                    float p2 = s[2 * ks + half][2], p3 = s[2 * ks + half][3];
                    __nv_bfloat16 h0 = __float2bfloat16(p0), h1 = __float2bfloat16(p1);
                    __nv_bfloat16 h2 = __float2bfloat16(p2), h3 = __float2bfloat16(p3);
                    pah[half * 2]     = pack_bf16(p0, p1);
                    pah[half * 2 + 1] = pack_bf16(p2, p3);
                    pal[half * 2]     = pack_bf16(p0 - __bfloat162float(h0),
                                                  p1 - __bfloat162float(h1));
                    pal[half * 2 + 1] = pack_bf16(p2 - __bfloat162float(h2),
                                                  p3 - __bfloat162float(h3));
                }
#pragma unroll
                for (int dp = 0; dp < 2; dp++) {
                    uint32_t rh[2][4], rl[2][4];
#pragma unroll
                    for (int j = 0; j < 2; j++) {
                        int dg = dp * 2 + j;
                        int key = ks * 16 + (lane & 15);
                        int ch = dg * 2 + (lane >> 4);
                        uint32_t a = st + 16384 + key * 128 + ((ch ^ (key & 7)) * 16);
                        ldm_x4_t(rh[j], a);            // Vh
                        ldm_x4_t(rl[j], a + 8192);     // Vl
                    }
                    float* o0 = o[4 * dp + 0];
                    float* o1 = o[4 * dp + 1];
                    float* o2 = o[4 * dp + 2];
                    float* o3 = o[4 * dp + 3];
                    // P_hi * V_hi
                    mma_bf16(o0, pah, rh[0][0], rh[0][1]);
                    mma_bf16(o1, pah, rh[0][2], rh[0][3]);
                    mma_bf16(o2, pah, rh[1][0], rh[1][1]);
                    mma_bf16(o3, pah, rh[1][2], rh[1][3]);
                    // P_hi * V_lo
                    mma_bf16(o0, pah, rl[0][0], rl[0][1]);
                    mma_bf16(o1, pah, rl[0][2], rl[0][3]);
                    mma_bf16(o2, pah, rl[1][0], rl[1][1]);
                    mma_bf16(o3, pah, rl[1][2], rl[1][3]);
                    // P_lo * V_hi
                    mma_bf16(o0, pal, rh[0][0], rh[0][1]);
                    mma_bf16(o1, pal, rh[0][2], rh[0][3]);
                    mma_bf16(o2, pal, rh[1][0], rh[1][1]);
                    mma_bf16(o3, pal, rh[1][2], rh[1][3]);
                }
            }
        }
        __syncthreads();
    }

    // ---- Finalize ----
    const float inv0 = 1.0f / l0v, inv1 = 1.0f / l1v;
    const int row0 = qbase + warp * 16 + (lane >> 2);
    const int col0 = h * HD + (lane & 3) * 2;
#pragma unroll
    for (int nf = 0; nf < 8; nf++) {
        int col = col0 + nf * 8;
        float a0 = o[nf][0] * inv0, a1 = o[nf][1] * inv0;
        float a2 = o[nf][2] * inv1, a3 = o[nf][3] * inv1;
        __nv_bfloat16 h0 = __float2bfloat16(a0), h1 = __float2bfloat16(a1);
        __nv_bfloat16 h2 = __float2bfloat16(a2), h3 = __float2bfloat16(a3);
        *reinterpret_cast<uint32_t*>(&Ch[(size_t)row0 * HID + col]) = pack_bf16(a0, a1);
        *reinterpret_cast<uint32_t*>(&Cl[(size_t)row0 * HID + col]) =
            pack_bf16(a0 - __bfloat162float(h0), a1 - __bfloat162float(h1));
        *reinterpret_cast<uint32_t*>(&Ch[(size_t)(row0 + 8) * HID + col]) = pack_bf16(a2, a3);
        *reinterpret_cast<uint32_t*>(&Cl[(size_t)(row0 + 8) * HID + col]) =
            pack_bf16(a2 - __bfloat162float(h2), a3 - __bfloat162float(h3));
    }
}

// ---------------------------------------------------------------------------
extern "C" void kernel_launch(void* const* d_in, const int* in_sizes, int n_in,
                              void* d_out, int out_size)
{
    const float* H  = (const float*)d_in[0];
    const float* Wa = (const float*)d_in[1];
    const float* ba = (const float*)d_in[2];
    const float* Wp = (const float*)d_in[3];
    const float* bp = (const float*)d_in[4];
    float* out = (float*)d_out;

    __nv_bfloat16 *Ah, *Al, *Wah, *Wal, *Wph, *Wpl, *Ch, *Cl;
    __nv_bfloat16 *Qh, *Ql, *Kh, *Kl, *Vh, *Vl;
    cudaGetSymbolAddress((void**)&Ah, g_Ah);
    cudaGetSymbolAddress((void**)&Al, g_Al);
    cudaGetSymbolAddress((void**)&Wah, g_Wah);
    cudaGetSymbolAddress((void**)&Wal, g_Wal);
    cudaGetSymbolAddress((void**)&Wph, g_Wph);
    cudaGetSymbolAddress((void**)&Wpl, g_Wpl);
    cudaGetSymbolAddress((void**)&Ch, g_Ch);
    cudaGetSymbolAddress((void**)&Cl, g_Cl);
    cudaGetSymbolAddress((void**)&Qh, g_Qh);
    cudaGetSymbolAddress((void**)&Ql, g_Ql);
    cudaGetSymbolAddress((void**)&Kh, g_Kh);
    cudaGetSymbolAddress((void**)&Kl, g_Kl);
    cudaGetSymbolAddress((void**)&Vh, g_Vh);
    cudaGetSymbolAddress((void**)&Vl, g_Vl);

    cudaFuncSetAttribute(gemm_mma_bf16x3,
                         cudaFuncAttributeMaxDynamicSharedMemorySize, NST * STAGE_BYTES);
    cudaFuncSetAttribute(attn_mma,
                         cudaFuncAttributeMaxDynamicSharedMemorySize, 65536);

    // 0) hi/lo conversions
    {
        int n4 = SEQ * HID / 4;
        cvt_hilo<<<(n4 + 255) / 256, 256>>>(H, Ah, Al, n4);
        dim3 gt1(QKV_N / 32, HID / 32), bt(32, 8);
        cvt_transpose<<<gt1, bt>>>(Wa, Wah, Wal, HID, QKV_N);
        dim3 gt2(HID / 32, HID / 32);
        cvt_transpose<<<gt2, bt>>>(Wp, Wph, Wpl, HID, HID);
    }

    // 1) QKV GEMM -> per-head hi/lo Q/K/V
    {
        dim3 g(QKV_N / 128, SEQ / 128);
        gemm_mma_bf16x3<<<g, 256, NST * STAGE_BYTES>>>(
            SEQ, QKV_N, HID, 1, Ah, Al, Wah, Wal, ba, nullptr,
            Qh, Ql, Kh, Kl, Vh, Vl);
    }

    // 2) Tensorized causal attention -> Ch/Cl
    {
        dim3 g(SEQ / 128, NH);
        attn_mma<<<g, 256, 65536>>>(Qh, Ql, Kh, Kl, Vh, Vl, Ch, Cl);
    }

    // 3) Output projection -> out (fp32 + bias)
    {
        dim3 g(HID / 128, SEQ / 128);
        gemm_mma_bf16x3<<<g, 256, NST * STAGE_BYTES>>>(
            SEQ, HID, HID, 0, Ch, Cl, Wph, Wpl, bp, out,
            nullptr, nullptr, nullptr, nullptr, nullptr, nullptr);
    }
}

// round 11
// speedup vs baseline: 1.0499x; 1.0499x over previous
#include <cuda_runtime.h>
#include <cuda_bf16.h>
#include <math_constants.h>
#include <cstdint>

#define SEQ 2048
#define HID 1024
#define NH  16
#define HD  64
#define QKV_N (3 * HID)

// ---------------------------------------------------------------------------
// Scratch (no dynamic allocation allowed)
// ---------------------------------------------------------------------------
__device__ __align__(128) __nv_bfloat16 g_Ah[SEQ * HID];
__device__ __align__(128) __nv_bfloat16 g_Al[SEQ * HID];
__device__ __align__(128) __nv_bfloat16 g_Wah[QKV_N * HID];
__device__ __align__(128) __nv_bfloat16 g_Wal[QKV_N * HID];
__device__ __align__(128) __nv_bfloat16 g_Wph[HID * HID];
__device__ __align__(128) __nv_bfloat16 g_Wpl[HID * HID];
__device__ __align__(128) __nv_bfloat16 g_Ch[SEQ * HID];
__device__ __align__(128) __nv_bfloat16 g_Cl[SEQ * HID];
// per-head QKV, bf16 hi/lo, layout [NH][SEQ][64]
__device__ __align__(128) __nv_bfloat16 g_Qh[NH * SEQ * HD];
__device__ __align__(128) __nv_bfloat16 g_Ql[NH * SEQ * HD];
__device__ __align__(128) __nv_bfloat16 g_Kh[NH * SEQ * HD];
__device__ __align__(128) __nv_bfloat16 g_Kl[NH * SEQ * HD];
__device__ __align__(128) __nv_bfloat16 g_Vh[NH * SEQ * HD];
__device__ __align__(128) __nv_bfloat16 g_Vl[NH * SEQ * HD];

// ---------------------------------------------------------------------------
// Helpers (baseline PTX only)
// ---------------------------------------------------------------------------
__device__ __forceinline__ uint32_t smem_u32(const void* p) {
    uint32_t a;
    asm("{ .reg .u64 t; cvta.to.shared.u64 t, %1; cvt.u32.u64 %0, t; }"
        : "=r"(a) : "l"(p));
    return a;
}
__device__ __forceinline__ void cp_async16(uint32_t dst, const void* src) {
    asm volatile("cp.async.cg.shared.global [%0], [%1], 16;"
                 :: "r"(dst), "l"(src));
}
#define CP_COMMIT() asm volatile("cp.async.commit_group;" ::: "memory")
#define CP_WAIT(n)  asm volatile("cp.async.wait_group %0;" :: "n"(n) : "memory")

__device__ __forceinline__ void ldm_x4(uint32_t* r, uint32_t addr) {
    asm volatile("ldmatrix.sync.aligned.m8n8.x4.shared.b16 {%0,%1,%2,%3}, [%4];"
                 : "=r"(r[0]), "=r"(r[1]), "=r"(r[2]), "=r"(r[3]) : "r"(addr));
}
__device__ __forceinline__ void ldm_x4_t(uint32_t* r, uint32_t addr) {
    asm volatile("ldmatrix.sync.aligned.m8n8.x4.trans.shared.b16 {%0,%1,%2,%3}, [%4];"
                 : "=r"(r[0]), "=r"(r[1]), "=r"(r[2]), "=r"(r[3]) : "r"(addr));
}
__device__ __forceinline__ void mma_bf16(float* d, const uint32_t* a,
                                         uint32_t b0, uint32_t b1) {
    asm volatile(
        "mma.sync.aligned.m16n8k16.row.col.f32.bf16.bf16.f32 "
        "{%0,%1,%2,%3}, {%4,%5,%6,%7}, {%8,%9}, {%0,%1,%2,%3};"
        : "+f"(d[0]), "+f"(d[1]), "+f"(d[2]), "+f"(d[3])
        : "r"(a[0]), "r"(a[1]), "r"(a[2]), "r"(a[3]), "r"(b0), "r"(b1));
}
__device__ __forceinline__ uint32_t pack_bf16(float a, float b) {
    __nv_bfloat162 t;
    t.x = __float2bfloat16(a);
    t.y = __float2bfloat16(b);
    return *reinterpret_cast<uint32_t*>(&t);
}

// ---------------------------------------------------------------------------
// Conversion kernels
// ---------------------------------------------------------------------------
__global__ void cvt_hilo(const float* __restrict__ x,
                         __nv_bfloat16* __restrict__ hi,
                         __nv_bfloat16* __restrict__ lo, int n4) {
    int i = blockIdx.x * blockDim.x + threadIdx.x;
    if (i >= n4) return;
    float4 v = reinterpret_cast<const float4*>(x)[i];
    __nv_bfloat16 h0 = __float2bfloat16(v.x), h1 = __float2bfloat16(v.y);
    __nv_bfloat16 h2 = __float2bfloat16(v.z), h3 = __float2bfloat16(v.w);
    uint2 hw, lw;
    hw.x = pack_bf16(v.x, v.y);
    hw.y = pack_bf16(v.z, v.w);
    lw.x = pack_bf16(v.x - __bfloat162float(h0), v.y - __bfloat162float(h1));
    lw.y = pack_bf16(v.z - __bfloat162float(h2), v.w - __bfloat162float(h3));
    reinterpret_cast<uint2*>(hi)[i] = hw;
    reinterpret_cast<uint2*>(lo)[i] = lw;
}

__global__ void cvt_transpose(const float* __restrict__ w,
                              __nv_bfloat16* __restrict__ th,
                              __nv_bfloat16* __restrict__ tl,
                              int K, int N) {
    __shared__ float tile[32][33];
    int n0 = blockIdx.x * 32, k0 = blockIdx.y * 32;
    int tx = threadIdx.x, ty = threadIdx.y;
#pragma unroll
    for (int j = 0; j < 4; j++)
        tile[ty + 8 * j][tx] = w[(size_t)(k0 + ty + 8 * j) * N + n0 + tx];
    __syncthreads();
#pragma unroll
    for (int j = 0; j < 4; j++) {
        float v = tile[tx][ty + 8 * j];
        __nv_bfloat16 h = __float2bfloat16(v);
        __nv_bfloat16 l = __float2bfloat16(v - __bfloat162float(h));
        size_t o = (size_t)(n0 + ty + 8 * j) * K + k0 + tx;
        th[o] = h;
        tl[o] = l;
    }
}

// ---------------------------------------------------------------------------
// bf16x3 GEMM: 512 threads (16 warps, 4 per SMSP), warp tile 32x32,
// 4-stage cp.async pipeline, term-major MMA order.
// mode 0: fp32 C + bias. mode 1: QKV split hi/lo per head.
// ---------------------------------------------------------------------------
#define PITCH 80
#define MAT_BYTES (128 * PITCH)
#define STAGE_BYTES (4 * MAT_BYTES)   // 40960
#define NST 4

__global__ __launch_bounds__(512, 1) void gemm_mma_bf16x3(
    int M, int N, int K, int mode,
    const __nv_bfloat16* __restrict__ Ah, const __nv_bfloat16* __restrict__ Al,
    const __nv_bfloat16* __restrict__ Bh, const __nv_bfloat16* __restrict__ Bl,
    const float* __restrict__ bias, float* __restrict__ C,
    __nv_bfloat16* __restrict__ qh, __nv_bfloat16* __restrict__ ql,
    __nv_bfloat16* __restrict__ kh, __nv_bfloat16* __restrict__ kl,
    __nv_bfloat16* __restrict__ vh, __nv_bfloat16* __restrict__ vl)
{
    extern __shared__ char sm[];
    const uint32_t sbase = smem_u32(sm);
    const int tid = threadIdx.x;
    const int lane = tid & 31;
    const int warp = tid >> 5;      // 0..15
    const int wm = warp & 3;        // 0..3 (32-row band)
    const int wn = warp >> 2;       // 0..3 (32-col band)
    const int m0 = blockIdx.y * 128;
    const int n0 = blockIdx.x * 128;

    const __nv_bfloat16* srcs[4] = {
        Ah + (size_t)m0 * K, Al + (size_t)m0 * K,
        Bh + (size_t)n0 * K, Bl + (size_t)n0 * K };

    float acc[2][4][4];
#pragma unroll
    for (int i = 0; i < 2; i++)
#pragma unroll
        for (int j = 0; j < 4; j++)
#pragma unroll
            for (int q = 0; q < 4; q++) acc[i][j][q] = 0.0f;

    auto load_stage = [&](int s, int kc) {
#pragma unroll
        for (int i = 0; i < 4; i++) {
            int t = tid + i * 512;
            int mat = t >> 9;            // 0..3
            int r = (t >> 2) & 127;
            int ch = t & 3;
            cp_async16(sbase + s * STAGE_BYTES + mat * MAT_BYTES + r * PITCH + ch * 16,
                       srcs[mat] + (size_t)r * K + kc * 32 + ch * 8);
        }
    };

    const int NC = K / 32;
#pragma unroll
    for (int s = 0; s < NST - 1; s++) {
        load_stage(s, s);
        CP_COMMIT();
    }

    const int g = lane >> 3;
    const int rl = lane & 7;

    for (int c = 0; c < NC; c++) {
        CP_WAIT(NST - 2);
        __syncthreads();

        const uint32_t st = sbase + (c % NST) * STAGE_BYTES;

#pragma unroll
        for (int k16 = 0; k16 < 2; k16++) {
            const int ch = k16 * 2 + (g >> 1);
            const int roff = rl + ((g & 1) << 3);

            uint32_t ah[2][4], al_[2][4];
#pragma unroll
            for (int mf = 0; mf < 2; mf++) {
                int row = wm * 32 + mf * 16 + roff;
                ldm_x4(ah[mf],  st + 0 * MAT_BYTES + row * PITCH + ch * 16);
                ldm_x4(al_[mf], st + 1 * MAT_BYTES + row * PITCH + ch * 16);
            }

            uint32_t bh_[4][2], bl_[4][2];
#pragma unroll
            for (int ng = 0; ng < 2; ng++) {
                int row = wn * 32 + ng * 16 + roff;
                uint32_t r4[4], r5[4];
                ldm_x4(r4, st + 2 * MAT_BYTES + row * PITCH + ch * 16);
                ldm_x4(r5, st + 3 * MAT_BYTES + row * PITCH + ch * 16);
                bh_[2 * ng][0] = r4[0];     bh_[2 * ng][1] = r4[2];
                bh_[2 * ng + 1][0] = r4[1]; bh_[2 * ng + 1][1] = r4[3];
                bl_[2 * ng][0] = r5[0];     bl_[2 * ng][1] = r5[2];
                bl_[2 * ng + 1][0] = r5[1]; bl_[2 * ng + 1][1] = r5[3];
            }

            // term-major: 8 independent accumulators per sweep
#pragma unroll
            for (int mf = 0; mf < 2; mf++)
#pragma unroll
                for (int nf = 0; nf < 4; nf++)
                    mma_bf16(acc[mf][nf], ah[mf],  bh_[nf][0], bh_[nf][1]);
#pragma unroll
            for (int mf = 0; mf < 2; mf++)
#pragma unroll
                for (int nf = 0; nf < 4; nf++)
                    mma_bf16(acc[mf][nf], ah[mf],  bl_[nf][0], bl_[nf][1]);
#pragma unroll
            for (int mf = 0; mf < 2; mf++)
#pragma unroll
                for (int nf = 0; nf < 4; nf++)
                    mma_bf16(acc[mf][nf], al_[mf], bh_[nf][0], bh_[nf][1]);
        }

        if (c + NST - 1 < NC)
            load_stage((c + NST - 1) % NST, c + NST - 1);
        CP_COMMIT();
    }

    // Epilogue
#pragma unroll
    for (int mf = 0; mf < 2; mf++) {
        int rbase = m0 + wm * 32 + mf * 16 + (lane >> 2);
#pragma unroll
        for (int nf = 0; nf < 4; nf++) {
            int col = n0 + wn * 32 + nf * 8 + (lane & 3) * 2;
            float2 bv = *reinterpret_cast<const float2*>(&bias[col]);
            float a0 = acc[mf][nf][0] + bv.x, a1 = acc[mf][nf][1] + bv.y;
            float a2 = acc[mf][nf][2] + bv.x, a3 = acc[mf][nf][3] + bv.y;
            if (mode == 0) {
                float2 o0 = {a0, a1}, o1 = {a2, a3};
                *reinterpret_cast<float2*>(&C[(size_t)rbase * N + col]) = o0;
                *reinterpret_cast<float2*>(&C[(size_t)(rbase + 8) * N + col]) = o1;
            } else {
                int sec = col >> 10;
                int head = (col & 1023) >> 6;
                int dim = col & 63;
                __nv_bfloat16* dh = (sec == 0) ? qh : (sec == 1) ? kh : vh;
                __nv_bfloat16* dl = (sec == 0) ? ql : (sec == 1) ? kl : vl;
                size_t o0 = ((size_t)head * SEQ + rbase) * HD + dim;
                size_t o1 = o0 + 8 * HD;
                __nv_bfloat16 h0 = __float2bfloat16(a0), h1 = __float2bfloat16(a1);
                __nv_bfloat16 h2 = __float2bfloat16(a2), h3 = __float2bfloat16(a3);
                *reinterpret_cast<uint32_t*>(&dh[o0]) = pack_bf16(a0, a1);
                *reinterpret_cast<uint32_t*>(&dl[o0]) =
                    pack_bf16(a0 - __bfloat162float(h0), a1 - __bfloat162float(h1));
                *reinterpret_cast<uint32_t*>(&dh[o1]) = pack_bf16(a2, a3);
                *reinterpret_cast<uint32_t*>(&dl[o1]) =
                    pack_bf16(a2 - __bfloat162float(h2), a3 - __bfloat162float(h3));
            }
        }
    }
}

// ---------------------------------------------------------------------------
// Tensorized causal flash attention, 128-query tiles, term-major MMA order.
// Block = (128 queries, 1 head), 256 threads = 8 warps x 16 rows. (unchanged)
// ---------------------------------------------------------------------------
__global__ __launch_bounds__(256, 1) void attn_mma(
    const __nv_bfloat16* __restrict__ Qh_, const __nv_bfloat16* __restrict__ Ql_,
    const __nv_bfloat16* __restrict__ Kh_, const __nv_bfloat16* __restrict__ Kl_,
    const __nv_bfloat16* __restrict__ Vh_, const __nv_bfloat16* __restrict__ Vl_,
    __nv_bfloat16* __restrict__ Ch, __nv_bfloat16* __restrict__ Cl)
{
    extern __shared__ char sm[];
    const uint32_t sb = smem_u32(sm);
    const int h = blockIdx.y;
    const int qb = blockIdx.x;
    const int tid = threadIdx.x;
    const int lane = tid & 31;
    const int warp = tid >> 5;
    const int qbase = qb * 128;
    const size_t hb = (size_t)h * SEQ * HD;
    const float scale = 0.125f;

    const __nv_bfloat16* kv[4] = { Kh_ + hb, Kl_ + hb, Vh_ + hb, Vl_ + hb };

    // ---- Load Q tile (128 rows, hi/lo) to smem, extract A-fragments ----
    for (int i = tid; i < 128 * 8; i += 256) {
        int r = i >> 3, ch = i & 7;
        uint32_t sw = (uint32_t)((ch ^ (r & 7)) * 16);
        const size_t go = hb + (size_t)(qbase + r) * HD + ch * 8;
        cp_async16(sb + r * 128 + sw, Qh_ + go);
        cp_async16(sb + 16384 + r * 128 + sw, Ql_ + go);
    }
    CP_COMMIT(); CP_WAIT(0);
    __syncthreads();

    uint32_t qh[4][4], ql[4][4];
    {
        int row = warp * 16 + (lane & 15);
#pragma unroll
        for (int ks = 0; ks < 4; ks++) {
            int ch = ks * 2 + (lane >> 4);
            uint32_t a = sb + row * 128 + ((ch ^ (row & 7)) * 16);
            ldm_x4(qh[ks], a);
            ldm_x4(ql[ks], a + 16384);
        }
    }
    __syncthreads();

    float o[8][4];
#pragma unroll
    for (int i = 0; i < 8; i++)
#pragma unroll
        for (int j = 0; j < 4; j++) o[i][j] = 0.0f;
    float m0v = -CUDART_INF_F, m1v = -CUDART_INF_F;
    float l0v = 0.0f, l1v = 0.0f;

    auto load_kv = [&](int s, int t) {
#pragma unroll
        for (int i = 0; i < 8; i++) {
            int idx = tid + i * 256;
            int mat = idx >> 9;
            int r = (idx >> 3) & 63;
            int ch = idx & 7;
            cp_async16(sb + s * 32768 + mat * 8192 + r * 128 + ((ch ^ (r & 7)) * 16),
                       kv[mat] + (size_t)(t * 64 + r) * HD + ch * 8);
        }
        CP_COMMIT();
    };

    load_kv(0, 0);

    const int ntiles = 2 * qb + 2;
    for (int t = 0; t < ntiles; t++) {
        if (t + 1 < ntiles) {
            load_kv((t + 1) & 1, t + 1);
            CP_WAIT(1);
        } else {
            CP_WAIT(0);
        }
        __syncthreads();

        const uint32_t st = sb + (t & 1) * 32768;
        const bool active = (t * 64 <= qbase + warp * 16 + 15);

        if (active) {
            // ---- S = Q K^T (hi/lo 3-MMA, kg pairs, term-major) ----
            float s[8][4];
#pragma unroll
            for (int i = 0; i < 8; i++)
#pragma unroll
                for (int j = 0; j < 4; j++) s[i][j] = 0.0f;

#pragma unroll
            for (int ks = 0; ks < 4; ks++) {
#pragma unroll
                for (int kp = 0; kp < 2; kp++) {
                    uint32_t rh[2][4], rl[2][4];
#pragma unroll
                    for (int j = 0; j < 2; j++) {
                        int key = (kp * 2 + j) * 16 + (lane & 15);
                        int ch = ks * 2 + (lane >> 4);
                        uint32_t a = st + key * 128 + ((ch ^ (key & 7)) * 16);
                        ldm_x4(rh[j], a);            // Kh
                        ldm_x4(rl[j], a + 8192);     // Kl
                    }
                    float* s0 = s[4 * kp + 0];
                    float* s1 = s[4 * kp + 1];
                    float* s2 = s[4 * kp + 2];
                    float* s3 = s[4 * kp + 3];
                    mma_bf16(s0, qh[ks], rh[0][0], rh[0][2]);
                    mma_bf16(s1, qh[ks], rh[0][1], rh[0][3]);
                    mma_bf16(s2, qh[ks], rh[1][0], rh[1][2]);
                    mma_bf16(s3, qh[ks], rh[1][1], rh[1][3]);
                    mma_bf16(s0, qh[ks], rl[0][0], rl[0][2]);
                    mma_bf16(s1, qh[ks], rl[0][1], rl[0][3]);
                    mma_bf16(s2, qh[ks], rl[1][0], rl[1][2]);
                    mma_bf16(s3, qh[ks], rl[1][1], rl[1][3]);
                    mma_bf16(s0, ql[ks], rh[0][0], rh[0][2]);
                    mma_bf16(s1, ql[ks], rh[0][1], rh[0][3]);
                    mma_bf16(s2, ql[ks], rh[1][0], rh[1][2]);
                    mma_bf16(s3, ql[ks], rh[1][1], rh[1][3]);
                }
            }

            // ---- scale + causal mask + online softmax ----
            const bool masked = (t >= 2 * qb);
            const int gr = lane >> 2;
            const int c2 = (lane & 3) * 2;
            const int gq0 = qbase + warp * 16 + gr;
            float mx0 = -CUDART_INF_F, mx1 = -CUDART_INF_F;
#pragma unroll
            for (int nf = 0; nf < 8; nf++) {
#pragma unroll
                for (int j = 0; j < 2; j++) {
                    s[nf][j]     *= scale;
                    s[nf][2 + j] *= scale;
                    if (masked) {
                        int gk = t * 64 + nf * 8 + c2 + j;
                        if (gk > gq0)     s[nf][j]     = -CUDART_INF_F;
                        if (gk > gq0 + 8) s[nf][2 + j] = -CUDART_INF_F;
                    }
                    mx0 = fmaxf(mx0, s[nf][j]);
                    mx1 = fmaxf(mx1, s[nf][2 + j]);
                }
            }
            mx0 = fmaxf(mx0, __shfl_xor_sync(0xffffffffu, mx0, 1));
            mx0 = fmaxf(mx0, __shfl_xor_sync(0xffffffffu, mx0, 2));
            mx1 = fmaxf(mx1, __shfl_xor_sync(0xffffffffu, mx1, 1));
            mx1 = fmaxf(mx1, __shfl_xor_sync(0xffffffffu, mx1, 2));

            float mn0 = fmaxf(m0v, mx0), mn1 = fmaxf(m1v, mx1);
            float sum0 = 0.0f, sum1 = 0.0f;
#pragma unroll
            for (int nf = 0; nf < 8; nf++) {
#pragma unroll
                for (int j = 0; j < 2; j++) {
                    float p0 = __expf(s[nf][j] - mn0);
                    float p1 = __expf(s[nf][2 + j] - mn1);
                    s[nf][j] = p0;
                    s[nf][2 + j] = p1;
                    sum0 += p0;
                    sum1 += p1;
                }
            }
            sum0 += __shfl_xor_sync(0xffffffffu, sum0, 1);
            sum0 += __shfl_xor_sync(0xffffffffu, sum0, 2);
            sum1 += __shfl_xor_sync(0xffffffffu, sum1, 1);
            sum1 += __shfl_xor_sync(0xffffffffu, sum1, 2);

            float corr0 = __expf(m0v - mn0), corr1 = __expf(m1v - mn1);
            l0v = l0v * corr0 + sum0;
            l1v = l1v * corr1 + sum1;
            m0v = mn0; m1v = mn1;
#pragma unroll
            for (int nf = 0; nf < 8; nf++) {
                o[nf][0] *= corr0; o[nf][1] *= corr0;
                o[nf][2] *= corr1; o[nf][3] *= corr1;
            }

            // ---- O += P V (hi/lo 3-MMA, dg pairs, term-major) ----
#pragma unroll
            for (int ks = 0; ks < 4; ks++) {
                uint32_t pah[4], pal[4];
#pragma unroll
                for (int half = 0; half < 2; half++) {
                    float p0 = s[2 * ks + half][0], p1 = s[2 * ks + half][1];
                    float p2 = s[2 * ks + half][2], p3 = s[2 * ks + half][3];
                    __nv_bfloat16 h0 = __float2bfloat16(p0), h1 = __float2bfloat16(p1);
                    __nv_bfloat16 h2 = __float2bfloat16(p2), h3 = __float2bfloat16(p3);
                    pah[half * 2]     = pack_bf16(p0, p1);
                    pah[half * 2 + 1] = pack_bf16(p2, p3);
                    pal[half * 2]     = pack_bf16(p0 - __bfloat162float(h0),
                                                  p1 - __bfloat162float(h1));
                    pal[half * 2 + 1] = pack_bf16(p2 - __bfloat162float(h2),
                                                  p3 - __bfloat162float(h3));
                }
#pragma unroll
                for (int dp = 0; dp < 2; dp++) {
                    uint32_t rh[2][4], rl[2][4];
#pragma unroll
                    for (int j = 0; j < 2; j++) {
                        int dg = dp * 2 + j;
                        int key = ks * 16 + (lane & 15);
                        int ch = dg * 2 + (lane >> 4);
                        uint32_t a = st + 16384 + key * 128 + ((ch ^ (key & 7)) * 16);
                        ldm_x4_t(rh[j], a);            // Vh
                        ldm_x4_t(rl[j], a + 8192);     // Vl
                    }
                    float* o0 = o[4 * dp + 0];
                    float* o1 = o[4 * dp + 1];
                    float* o2 = o[4 * dp + 2];
                    float* o3 = o[4 * dp + 3];
                    mma_bf16(o0, pah, rh[0][0], rh[0][1]);
                    mma_bf16(o1, pah, rh[0][2], rh[0][3]);
                    mma_bf16(o2, pah, rh[1][0], rh[1][1]);
                    mma_bf16(o3, pah, rh[1][2], rh[1][3]);
                    mma_bf16(o0, pah, rl[0][0], rl[0][1]);
                    mma_bf16(o1, pah, rl[0][2], rl[0][3]);
                    mma_bf16(o2, pah, rl[1][0], rl[1][1]);
                    mma_bf16(o3, pah, rl[1][2], rl[1][3]);
                    mma_bf16(o0, pal, rh[0][0], rh[0][1]);
                    mma_bf16(o1, pal, rh[0][2], rh[0][3]);
                    mma_bf16(o2, pal, rh[1][0], rh[1][1]);
                    mma_bf16(o3, pal, rh[1][2], rh[1][3]);
                }
            }
        }
        __syncthreads();
    }

    // ---- Finalize ----
    const float inv0 = 1.0f / l0v, inv1 = 1.0f / l1v;
    const int row0 = qbase + warp * 16 + (lane >> 2);
    const int col0 = h * HD + (lane & 3) * 2;
#pragma unroll
    for (int nf = 0; nf < 8; nf++) {
        int col = col0 + nf * 8;
        float a0 = o[nf][0] * inv0, a1 = o[nf][1] * inv0;
        float a2 = o[nf][2] * inv1, a3 = o[nf][3] * inv1;
        __nv_bfloat16 h0 = __float2bfloat16(a0), h1 = __float2bfloat16(a1);
        __nv_bfloat16 h2 = __float2bfloat16(a2), h3 = __float2bfloat16(a3);
        *reinterpret_cast<uint32_t*>(&Ch[(size_t)row0 * HID + col]) = pack_bf16(a0, a1);
        *reinterpret_cast<uint32_t*>(&Cl[(size_t)row0 * HID + col]) =
            pack_bf16(a0 - __bfloat162float(h0), a1 - __bfloat162float(h1));
        *reinterpret_cast<uint32_t*>(&Ch[(size_t)(row0 + 8) * HID + col]) = pack_bf16(a2, a3);
        *reinterpret_cast<uint32_t*>(&Cl[(size_t)(row0 + 8) * HID + col]) =
            pack_bf16(a2 - __bfloat162float(h2), a3 - __bfloat162float(h3));
    }
}

// ---------------------------------------------------------------------------
extern "C" void kernel_launch(void* const* d_in, const int* in_sizes, int n_in,
                              void* d_out, int out_size)
{
    const float* H  = (const float*)d_in[0];
    const float* Wa = (const float*)d_in[1];
    const float* ba = (const float*)d_in[2];
    const float* Wp = (const float*)d_in[3];
    const float* bp = (const float*)d_in[4];
    float* out = (float*)d_out;

    __nv_bfloat16 *Ah, *Al, *Wah, *Wal, *Wph, *Wpl, *Ch, *Cl;
    __nv_bfloat16 *Qh, *Ql, *Kh, *Kl, *Vh, *Vl;
    cudaGetSymbolAddress((void**)&Ah, g_Ah);
    cudaGetSymbolAddress((void**)&Al, g_Al);
    cudaGetSymbolAddress((void**)&Wah, g_Wah);
    cudaGetSymbolAddress((void**)&Wal, g_Wal);
    cudaGetSymbolAddress((void**)&Wph, g_Wph);
    cudaGetSymbolAddress((void**)&Wpl, g_Wpl);
    cudaGetSymbolAddress((void**)&Ch, g_Ch);
    cudaGetSymbolAddress((void**)&Cl, g_Cl);
    cudaGetSymbolAddress((void**)&Qh, g_Qh);
    cudaGetSymbolAddress((void**)&Ql, g_Ql);
    cudaGetSymbolAddress((void**)&Kh, g_Kh);
    cudaGetSymbolAddress((void**)&Kl, g_Kl);
    cudaGetSymbolAddress((void**)&Vh, g_Vh);
    cudaGetSymbolAddress((void**)&Vl, g_Vl);

    cudaFuncSetAttribute(gemm_mma_bf16x3,
                         cudaFuncAttributeMaxDynamicSharedMemorySize, NST * STAGE_BYTES);
    cudaFuncSetAttribute(attn_mma,
                         cudaFuncAttributeMaxDynamicSharedMemorySize, 65536);

    // 0) hi/lo conversions
    {
        int n4 = SEQ * HID / 4;
        cvt_hilo<<<(n4 + 255) / 256, 256>>>(H, Ah, Al, n4);
        dim3 gt1(QKV_N / 32, HID / 32), bt(32, 8);
        cvt_transpose<<<gt1, bt>>>(Wa, Wah, Wal, HID, QKV_N);
        dim3 gt2(HID / 32, HID / 32);
        cvt_transpose<<<gt2, bt>>>(Wp, Wph, Wpl, HID, HID);
    }

    // 1) QKV GEMM -> per-head hi/lo Q/K/V
    {
        dim3 g(QKV_N / 128, SEQ / 128);
        gemm_mma_bf16x3<<<g, 512, NST * STAGE_BYTES>>>(
            SEQ, QKV_N, HID, 1, Ah, Al, Wah, Wal, ba, nullptr,
            Qh, Ql, Kh, Kl, Vh, Vl);
    }

    // 2) Tensorized causal attention -> Ch/Cl
    {
        dim3 g(SEQ / 128, NH);
        attn_mma<<<g, 256, 65536>>>(Qh, Ql, Kh, Kl, Vh, Vl, Ch, Cl);
    }

    // 3) Output projection -> out (fp32 + bias)
    {
        dim3 g(HID / 128, SEQ / 128);
        gemm_mma_bf16x3<<<g, 512, NST * STAGE_BYTES>>>(
            SEQ, HID, HID, 0, Ch, Cl, Wph, Wpl, bp, out,
            nullptr, nullptr, nullptr, nullptr, nullptr, nullptr);
    }
}